// round 6
// baseline (speedup 1.0000x reference)
#include <cuda_runtime.h>
#include <cstdint>

#define BB 32
#define T_IN 512
#define NT 426
#define NC 1629          // 543*3
#define JF 53
#define XPART ((size_t)BB * NT * NC)   // 22,206,528

// ---- device scratch (no allocation allowed) ----
__device__ int   g_n[BB * NT];
__device__ int   g_rows[BB * NT][8];
__device__ float g_w[BB * NT][8];

__device__ __forceinline__ bool read_bool_m(const void* p, int i, int m) {
    if (m == 0) return ((const unsigned char*)p)[i] != 0;
    if (m == 1) return ((const int*)p)[i] != 0;
    return ((const float*)p)[i] != 0.0f;
}

// One block per batch. Phases:
//  1) bool-dtype detect (each block scans first 3408 words of keep -- safe for
//     uint8/int32/float32 element sizes; redundancy avoids a global sync)
//  2) warp-ballot prefix scan of keep_mask -> kept index list in SHARED
//  3) per-t (row, weight) list construction + mask output
__global__ __launch_bounds__(448) void prep_kernel(
    const void* __restrict__ mask,
    const void* __restrict__ keep,
    const float* __restrict__ bj,
    float* __restrict__ out)
{
    __shared__ int s_bad, s_anyf, s_mode;
    __shared__ int s_kept[NT];
    __shared__ int s_K;
    __shared__ int wsum[14];

    int b = blockIdx.x;
    int t = threadIdx.x;                 // 448 threads, 14 warps

    // ---- phase 1: dtype detection ----
    if (t == 0) { s_bad = 0; s_anyf = 0; }
    __syncthreads();
    {
        const unsigned* w = (const unsigned*)keep;
        int lb = 0, lf = 0;
        const int nwords = (BB * NT) / 4;        // 3408: min buffer size across dtypes
        for (int i = t; i < nwords; i += 448) {
            unsigned v = w[i];
            lb |= (v != 0u && v != 1u);
            lf |= (v == 0x3F800000u);
        }
        if (lb) atomicOr(&s_bad, 1);
        if (lf) atomicOr(&s_anyf, 1);
    }
    __syncthreads();
    if (t == 0) s_mode = s_bad ? (s_anyf ? 2 : 0) : 1;
    __syncthreads();
    int m = s_mode;

    // ---- phase 2: kept-index scan ----
    bool kb = (t < NT) ? read_bool_m(keep, b * NT + t, m) : false;
    unsigned bal = __ballot_sync(0xFFFFFFFFu, kb);
    int lane = t & 31, wid = t >> 5;
    int pre = __popc(bal & ((1u << lane) - 1u));
    if (lane == 0) wsum[wid] = __popc(bal);
    __syncthreads();
    int base = 0;
    for (int i = 0; i < wid; i++) base += wsum[i];
    if (kb) s_kept[base + pre] = t;
    if (t == 0) {
        int K = 0;
        for (int i = 0; i < 14; i++) K += wsum[i];
        s_K = K;
    }
    __syncthreads();

    // ---- phase 3: setup ----
    if (t >= NT) return;
    int bt = b * NT + t;
    int K = s_K;

    // mask output
    int nidx = (int)floorf((float)t * (512.0f / 426.0f));
    if (nidx > T_IN - 1) nidx = T_IN - 1;
    bool mo = read_bool_m(mask, b * T_IN + nidx, m) && kb;
    out[XPART + (size_t)bt] = mo ? 1.0f : 0.0f;

    // jitter (scale-then-lerp matches reference rounding)
    float jit = 0.0f;
    if (t > 0) {
        float sj = (float)t * (52.0f / 425.0f);
        int ij = (int)floorf(sj);
        if (ij > JF - 2) ij = JF - 2;
        if (ij < 0) ij = 0;
        float fj = sj - (float)ij;
        float j0 = bj[b * JF + ij]     * 0.02f;
        float j1 = bj[b * JF + ij + 1] * 0.02f;
        jit = j0 * (1.0f - fj) + j1 * fj;
    }

    int   rows[8];
    float wv[8];
    int n = 0;

    auto push = [&](int r, float w) {
        for (int i = 0; i < n; i++)
            if (rows[i] == r) { wv[i] += w; return; }
        rows[n] = r; wv[n] = w; n++;
    };
    auto add_x1 = [&](int tau, float c) {
        float s = (float)tau * (511.0f / 425.0f);
        int i0 = (int)floorf(s);
        if (i0 > T_IN - 2) i0 = T_IN - 2;
        if (i0 < 0) i0 = 0;
        float f = s - (float)i0;
        push(i0,     c * (1.0f - f));
        push(i0 + 1, c * f);
    };
    auto add_x2 = [&](int tau, float c) {
        if (read_bool_m(keep, b * NT + tau, m)) {
            add_x1(tau, c);
        } else {
            float s = ((float)tau * (float)(K - 1)) / 425.0f;
            int r0 = (int)floorf(s);
            if (r0 > K - 2) r0 = K - 2;
            if (r0 < 0) r0 = 0;
            float fd = s - (float)r0;
            add_x1(s_kept[r0],     c * (1.0f - fd));
            add_x1(s_kept[r0 + 1], c * fd);
        }
    };

    if (t == 0) {
        add_x2(0, 1.0f);
    } else {
        add_x2(t,     1.0f + jit);
        add_x2(t - 1, -jit);
    }
    g_n[bt] = n;
    #pragma unroll
    for (int i = 0; i < 8; i++) {
        g_rows[bt][i] = (i < n) ? rows[i] : 0;
        g_w[bt][i]    = (i < n) ? wv[i]   : 0.0f;
    }
}

// Pure streaming: out[b,t,:] = sum_i w_i * x[b,row_i,:] + noise*.01 + spatial*.005
// 416 threads x 4 elems = 1664 >= 1629: single pass, 4 independent FMA chains.
__global__ __launch_bounds__(416) void fused_kernel(
    const float* __restrict__ x,
    const float* __restrict__ noise,
    const float* __restrict__ sp,
    float* __restrict__ out)
{
    int bt = blockIdx.x;
    int b = bt / NT;

    __shared__ int   srows[8];
    __shared__ float sw[8];
    __shared__ int   snum;

    if (threadIdx.x == 0) snum = g_n[bt];
    if (threadIdx.x < 8) {
        srows[threadIdx.x] = g_rows[bt][threadIdx.x];
        sw[threadIdx.x]    = g_w[bt][threadIdx.x];
    }
    __syncthreads();

    int n = snum;
    const float* xb = x     + (size_t)b * T_IN * NC;
    const float* nz = noise + (size_t)bt * NC;
    const float* sb = sp    + (size_t)b * NC;
    float*       ob = out   + (size_t)bt * NC;

    int e = threadIdx.x * 4;
    if (e + 3 < NC) {
        float a0 = nz[e]   * 0.01f + sb[e]   * 0.005f;
        float a1 = nz[e+1] * 0.01f + sb[e+1] * 0.005f;
        float a2 = nz[e+2] * 0.01f + sb[e+2] * 0.005f;
        float a3 = nz[e+3] * 0.01f + sb[e+3] * 0.005f;
        for (int i = 0; i < n; i++) {
            const float* xr = xb + (size_t)srows[i] * NC + e;
            float w = sw[i];
            a0 = fmaf(w, xr[0], a0);
            a1 = fmaf(w, xr[1], a1);
            a2 = fmaf(w, xr[2], a2);
            a3 = fmaf(w, xr[3], a3);
        }
        ob[e]   = a0;
        ob[e+1] = a1;
        ob[e+2] = a2;
        ob[e+3] = a3;
    } else {
        for (int k = 0; k < 4; k++) {
            int ee = e + k;
            if (ee < NC) {
                float a = nz[ee] * 0.01f + sb[ee] * 0.005f;
                for (int i = 0; i < n; i++)
                    a = fmaf(sw[i], xb[(size_t)srows[i] * NC + ee], a);
                ob[ee] = a;
            }
        }
    }
}

extern "C" void kernel_launch(void* const* d_in, const int* in_sizes, int n_in,
                              void* d_out, int out_size) {
    const float* x     = (const float*)d_in[0];
    const void*  mask  = d_in[1];
    const void*  keep  = d_in[2];
    const float* bj    = (const float*)d_in[3];
    const float* noise = (const float*)d_in[4];
    const float* sp    = (const float*)d_in[5];
    float* out = (float*)d_out;

    prep_kernel<<<BB, 448>>>(mask, keep, bj, out);
    fused_kernel<<<BB * NT, 416>>>(x, noise, sp, out);
}

// round 7
// speedup vs baseline: 1.7530x; 1.7530x over previous
#include <cuda_runtime.h>
#include <cstdint>

#define BB 32
#define T_IN 512
#define NT 426
#define NC 1629          // 543*3
#define JF 53
#define XPART ((size_t)BB * NT * NC)   // 22,206,528
#define NCHUNK 7         // 7*256 = 1792 >= 1629

// ---- device scratch (SoA for coalesced prep writes) ----
__device__ int   g_n[BB * NT];
__device__ int   g_rows[8][BB * NT];
__device__ float g_w[8][BB * NT];

__device__ __forceinline__ bool read_bool_m(const void* p, int i, int m) {
    if (m == 0) return ((const unsigned char*)p)[i] != 0;
    if (m == 1) return ((const int*)p)[i] != 0;
    return ((const float*)p)[i] != 0.0f;
}

// One block per batch. Phases:
//  1) bool-dtype detect (each block scans first 3408 words of keep -- safe for
//     uint8/int32/float32 element sizes; redundancy avoids a global sync)
//  2) warp-ballot prefix scan of keep_mask -> kept index list in SHARED
//  3) per-t (row, weight) list construction + mask output
__global__ __launch_bounds__(448) void prep_kernel(
    const void* __restrict__ mask,
    const void* __restrict__ keep,
    const float* __restrict__ bj,
    float* __restrict__ out)
{
    __shared__ int s_bad, s_anyf, s_mode;
    __shared__ int s_kept[NT];
    __shared__ int s_K;
    __shared__ int wsum[14];

    int b = blockIdx.x;
    int t = threadIdx.x;                 // 448 threads, 14 warps

    // ---- phase 1: dtype detection ----
    if (t == 0) { s_bad = 0; s_anyf = 0; }
    __syncthreads();
    {
        const unsigned* w = (const unsigned*)keep;
        int lb = 0, lf = 0;
        const int nwords = (BB * NT) / 4;        // 3408: min buffer size across dtypes
        for (int i = t; i < nwords; i += 448) {
            unsigned v = w[i];
            lb |= (v != 0u && v != 1u);
            lf |= (v == 0x3F800000u);
        }
        if (lb) atomicOr(&s_bad, 1);
        if (lf) atomicOr(&s_anyf, 1);
    }
    __syncthreads();
    if (t == 0) s_mode = s_bad ? (s_anyf ? 2 : 0) : 1;
    __syncthreads();
    int m = s_mode;

    // ---- phase 2: kept-index scan ----
    bool kb = (t < NT) ? read_bool_m(keep, b * NT + t, m) : false;
    unsigned bal = __ballot_sync(0xFFFFFFFFu, kb);
    int lane = t & 31, wid = t >> 5;
    int pre = __popc(bal & ((1u << lane) - 1u));
    if (lane == 0) wsum[wid] = __popc(bal);
    __syncthreads();
    int base = 0;
    for (int i = 0; i < wid; i++) base += wsum[i];
    if (kb) s_kept[base + pre] = t;
    if (t == 0) {
        int K = 0;
        for (int i = 0; i < 14; i++) K += wsum[i];
        s_K = K;
    }
    __syncthreads();

    // ---- phase 3: setup ----
    if (t >= NT) return;
    int bt = b * NT + t;
    int K = s_K;

    // mask output
    int nidx = (int)floorf((float)t * (512.0f / 426.0f));
    if (nidx > T_IN - 1) nidx = T_IN - 1;
    bool mo = read_bool_m(mask, b * T_IN + nidx, m) && kb;
    out[XPART + (size_t)bt] = mo ? 1.0f : 0.0f;

    // jitter (scale-then-lerp matches reference rounding)
    float jit = 0.0f;
    if (t > 0) {
        float sj = (float)t * (52.0f / 425.0f);
        int ij = (int)floorf(sj);
        if (ij > JF - 2) ij = JF - 2;
        if (ij < 0) ij = 0;
        float fj = sj - (float)ij;
        float j0 = bj[b * JF + ij]     * 0.02f;
        float j1 = bj[b * JF + ij + 1] * 0.02f;
        jit = j0 * (1.0f - fj) + j1 * fj;
    }

    int   rows[8];
    float wv[8];
    int n = 0;

    auto push = [&](int r, float w) {
        for (int i = 0; i < n; i++)
            if (rows[i] == r) { wv[i] += w; return; }
        rows[n] = r; wv[n] = w; n++;
    };
    auto add_x1 = [&](int tau, float c) {
        float s = (float)tau * (511.0f / 425.0f);
        int i0 = (int)floorf(s);
        if (i0 > T_IN - 2) i0 = T_IN - 2;
        if (i0 < 0) i0 = 0;
        float f = s - (float)i0;
        push(i0,     c * (1.0f - f));
        push(i0 + 1, c * f);
    };
    auto add_x2 = [&](int tau, float c) {
        if (read_bool_m(keep, b * NT + tau, m)) {
            add_x1(tau, c);
        } else {
            float s = ((float)tau * (float)(K - 1)) / 425.0f;
            int r0 = (int)floorf(s);
            if (r0 > K - 2) r0 = K - 2;
            if (r0 < 0) r0 = 0;
            float fd = s - (float)r0;
            add_x1(s_kept[r0],     c * (1.0f - fd));
            add_x1(s_kept[r0 + 1], c * fd);
        }
    };

    if (t == 0) {
        add_x2(0, 1.0f);
    } else {
        add_x2(t,     1.0f + jit);
        add_x2(t - 1, -jit);
    }
    g_n[bt] = n;
    #pragma unroll
    for (int i = 0; i < 8; i++) {
        g_rows[i][bt] = (i < n) ? rows[i] : 0;
        g_w[i][bt]    = (i < n) ? wv[i]   : 0.0f;
    }
}

// Pure streaming: out[b,t,:] = sum_i w_i * x[b,row_i,:] + noise*.01 + spatial*.005
// Coalesced chunks: e = tid + k*256 (1 L1 wavefront per LDG), 7 independent
// accumulator chains -> MLP ~ 7*n. Streaming data (__ldcs/__stcs) bypasses L2
// retention so the reused x tensor stays resident.
__global__ __launch_bounds__(256) void fused_kernel(
    const float* __restrict__ x,
    const float* __restrict__ noise,
    const float* __restrict__ sp,
    float* __restrict__ out)
{
    int bt = blockIdx.x;
    int b = bt / NT;

    __shared__ int   srows[8];
    __shared__ float sw[8];
    __shared__ int   snum;

    if (threadIdx.x == 0) snum = g_n[bt];
    if (threadIdx.x < 8) {
        srows[threadIdx.x] = g_rows[threadIdx.x][bt];
        sw[threadIdx.x]    = g_w[threadIdx.x][bt];
    }
    __syncthreads();

    int n = snum;
    const float* xb = x     + (size_t)b * T_IN * NC;
    const float* nz = noise + (size_t)bt * NC;
    const float* sb = sp    + (size_t)b * NC;
    float*       ob = out   + (size_t)bt * NC;

    int tid = threadIdx.x;
    float acc[NCHUNK];
    #pragma unroll
    for (int k = 0; k < NCHUNK; k++) {
        int e = tid + k * 256;
        acc[k] = (e < NC) ? fmaf(__ldcs(nz + e), 0.01f, sb[e] * 0.005f) : 0.0f;
    }

    for (int i = 0; i < n; i++) {
        const float* xr = xb + (size_t)srows[i] * NC;
        float w = sw[i];
        #pragma unroll
        for (int k = 0; k < NCHUNK; k++) {
            int e = tid + k * 256;
            if (e < NC) acc[k] = fmaf(w, __ldg(xr + e), acc[k]);
        }
    }

    #pragma unroll
    for (int k = 0; k < NCHUNK; k++) {
        int e = tid + k * 256;
        if (e < NC) __stcs(ob + e, acc[k]);
    }
}

extern "C" void kernel_launch(void* const* d_in, const int* in_sizes, int n_in,
                              void* d_out, int out_size) {
    const float* x     = (const float*)d_in[0];
    const void*  mask  = d_in[1];
    const void*  keep  = d_in[2];
    const float* bj    = (const float*)d_in[3];
    const float* noise = (const float*)d_in[4];
    const float* sp    = (const float*)d_in[5];
    float* out = (float*)d_out;

    prep_kernel<<<BB, 448>>>(mask, keep, bj, out);
    fused_kernel<<<BB * NT, 256>>>(x, noise, sp, out);
}